// round 16
// baseline (speedup 1.0000x reference)
#include <cuda_runtime.h>
#include <cuda_fp16.h>
#include <cstdint>

#define N_NODES 50000
#define N_EDGES 800000
#define T_DIM   8
#define NF_IN   32
#define NH1     40
#define NH2     64
#define NF_OUT  64

// Scratch (device globals; allocation-free per harness rules)
__device__ __align__(16) __half g_thf  [N_NODES * 256];   // tf^T * onorm, [n][t][32], fp16
__device__ __align__(16) __half g_hbufB[N_NODES * 320];   // layer1 out [n][t][40], fp16
__device__ __align__(16) __half g_hbufA[N_NODES * 512];   // layer2 out [n][t][64], fp16
__device__ float g_onorm[N_NODES];
__device__ float g_inorm[N_NODES];
__device__ int   g_odeg [N_NODES];   // zero on entry (static init + self-restore)
__device__ int   g_indeg[N_NODES];   // zero on entry (static init + self-restore)
__device__ int   g_offsets[N_NODES + 1];
__device__ int   g_cursor [N_NODES];
__device__ __align__(16) int g_esrc [N_EDGES];
// i-pair-interleaved weights: [half][p][og] float4 = {w[2p][o],w[2p+1][o],w[2p][o+1],w[2p+1][o+1]}, o=og*4+half*2
__device__ __align__(16) float g_W1p[2 * 16 * 10 * 4];    // 1280
__device__ __align__(16) float g_W2p[2 * 20 * 16 * 4];    // 2560
__device__ __align__(16) float g_Wfp[2 * 96 * 16 * 4];    // 12288 (fused W3*Wc)
__device__ __align__(16) float g_biasm[64];               // bias for t in 1..6
__device__ __align__(16) float g_bias0[64];               // bias for t == 0
__device__ __align__(16) float g_bias7[64];               // bias for t == 7

static inline int cdiv(int a, int b) { return (a + b - 1) / b; }

__device__ __forceinline__ unsigned int pack_half2(float a, float b) {
    __half2 h = __floats2half2_rn(a, b);
    return *reinterpret_cast<unsigned int*>(&h);
}

// ---- packed f32x2 helpers (Blackwell FFMA2) ----
__device__ __forceinline__ unsigned long long f2pack(float lo, float hi) {
    unsigned long long r;
    asm("mov.b64 %0, {%1, %2};" : "=l"(r) : "f"(lo), "f"(hi));
    return r;
}
__device__ __forceinline__ void f2unpack(unsigned long long v, float& lo, float& hi) {
    asm("mov.b64 {%0, %1}, %2;" : "=f"(lo), "=f"(hi) : "l"(v));
}
__device__ __forceinline__ void ffma2(unsigned long long& d,
                                      unsigned long long a, unsigned long long b) {
    asm("fma.rn.f32x2 %0, %1, %2, %3;" : "=l"(d) : "l"(a), "l"(b), "l"(d));
}
__device__ __forceinline__ float f2sum(unsigned long long v) {
    float lo, hi; f2unpack(v, lo, hi); return lo + hi;
}

// ---------------------------------------------------------------------------
// Launch 0: degree histogram (gid < N_EDGES) + weight preprocessing (rest).
__global__ void k_degprep(const int* __restrict__ src, const int* __restrict__ dst,
                          const float* __restrict__ W1, const float* __restrict__ W2,
                          const float* __restrict__ W3, const float* __restrict__ Wc,
                          const float* __restrict__ b3, const float* __restrict__ bc) {
    int gid = blockIdx.x * blockDim.x + threadIdx.x;
    if (gid < N_EDGES) {
        atomicAdd(&g_odeg[src[gid]], 1);
        atomicAdd(&g_indeg[dst[gid]], 1);
        return;
    }
    int j = gid - N_EDGES;
    if (j < 12288) {
        // Wfp interleaved: fused Wf[kc][i][o] = sum_q W3[i][q] * Wc[o][q][kc]
        int half = j / 6144, r = j % 6144;
        int p = r / 64, rr = r % 64;
        int og = rr / 4, c = rr & 3;
        int d = 2 * p + (c & 1);
        int kc = d / 64, ii = d % 64;
        int o = og * 4 + half * 2 + (c >> 1);
        const float* w3r = W3 + ii * 64;
        const float* wcr = Wc + o * 192 + kc;   // Wc[o][q][kc], stride 3 over q
        float s = 0.0f;
        #pragma unroll 8
        for (int q = 0; q < 64; ++q)
            s = fmaf(w3r[q], wcr[q * 3], s);
        g_Wfp[j] = s;
    } else if (j < 12288 + 64) {
        int o = j - 12288;
        const float* wcr = Wc + o * 192;
        float B0 = 0.0f, B1 = 0.0f, B2 = 0.0f;
        #pragma unroll 8
        for (int q = 0; q < 64; ++q) {
            float bq = b3[q];
            B0 = fmaf(bq, wcr[q * 3 + 0], B0);
            B1 = fmaf(bq, wcr[q * 3 + 1], B1);
            B2 = fmaf(bq, wcr[q * 3 + 2], B2);
        }
        float base = bc[o];
        g_biasm[o] = base + B0 + B1 + B2;
        g_bias0[o] = base + B1 + B2;       // t=0: k=0 invalid
        g_bias7[o] = base + B0 + B1;       // t=7: k=2 invalid
    } else if (j < 12288 + 64 + 1280) {
        int f = j - 12352;                 // W1p: P=16, OG=10
        int half = f / 640, r = f % 640;
        int p = r / 40, rr = r % 40;
        int og = rr / 4, c = rr & 3;
        int i = 2 * p + (c & 1);
        int o = og * 4 + half * 2 + (c >> 1);
        g_W1p[f] = W1[i * NH1 + o];
    } else if (j < 12288 + 64 + 1280 + 2560) {
        int f = j - 13632;                 // W2p: P=20, OG=16
        int half = f / 1280, r = f % 1280;
        int p = r / 64, rr = r % 64;
        int og = rr / 4, c = rr & 3;
        int i = 2 * p + (c & 1);
        int o = og * 4 + half * 2 + (c >> 1);
        g_W2p[f] = W2[i * NH2 + o];
    }
}

// Launch 1: single-block CSR prologue (scan + norms — proven)
__global__ void k_scanall() {
    __shared__ int wsum[32];
    __shared__ int s_carry;
    int lane = threadIdx.x & 31, wid = threadIdx.x >> 5;

    if (threadIdx.x == 0) s_carry = 0;
    __syncthreads();

    for (int base = 0; base < N_NODES; base += 1024) {
        int idx = base + threadIdx.x;
        int v = (idx < N_NODES) ? g_indeg[idx] : 0;
        int x = v;
        #pragma unroll
        for (int o = 1; o < 32; o <<= 1) {
            int y = __shfl_up_sync(0xffffffffu, x, o);
            if (lane >= o) x += y;
        }
        if (lane == 31) wsum[wid] = x;
        __syncthreads();
        if (wid == 0) {
            int s = wsum[lane];
            #pragma unroll
            for (int o = 1; o < 32; o <<= 1) {
                int y = __shfl_up_sync(0xffffffffu, s, o);
                if (lane >= o) s += y;
            }
            wsum[lane] = s;
        }
        __syncthreads();
        int carry = s_carry;
        int wbase = (wid > 0) ? wsum[wid - 1] : 0;
        int excl = carry + wbase + x - v;
        if (idx < N_NODES) {
            g_offsets[idx] = excl;
            g_cursor[idx]  = excl;
            g_onorm[idx] = rsqrtf(fmaxf((float)g_odeg[idx], 1.0f));
            g_inorm[idx] = rsqrtf(fmaxf((float)v, 1.0f));
        }
        __syncthreads();
        if (threadIdx.x == 1023) s_carry = carry + wbase + x;
        __syncthreads();
    }
    if (threadIdx.x == 0) g_offsets[N_NODES] = s_carry;
}

// Launch 2: fill CSR (gid < N_EDGES) + tf transpose * onorm -> fp16 (all blocks)
__global__ void k_fill(const int* __restrict__ src, const int* __restrict__ dst,
                       const float* __restrict__ tf) {
    __shared__ float sh[8][32 * 9];     // per-warp node tile, padded [f][t]
    int gid = blockIdx.x * blockDim.x + threadIdx.x;
    if (gid < N_EDGES) {                // first 3125 blocks
        int pos = atomicAdd(&g_cursor[dst[gid]], 1);
        g_esrc[pos] = src[gid];
    }

    int w = threadIdx.x >> 5, lane = threadIdx.x & 31;
    int node = blockIdx.x * 8 + w;      // 6250*8 = 50000 exactly
    const float4* src4 = reinterpret_cast<const float4*>(tf + (size_t)node * 256);
    #pragma unroll
    for (int h = 0; h < 2; ++h) {
        float4 v = __ldg(&src4[h * 32 + lane]);
        int l = (h * 32 + lane) * 4;    // linear [f][t] index
        int f = l >> 3, t = l & 7;
        float* p = &sh[w][f * 9 + t];
        p[0] = v.x; p[1] = v.y; p[2] = v.z; p[3] = v.w;
    }
    __syncwarp();
    float onrm = __ldg(&g_onorm[node]);
    int t = lane >> 2, f0 = (lane & 3) * 8;
    float v[8];
    #pragma unroll
    for (int m = 0; m < 8; ++m) v[m] = sh[w][(f0 + m) * 9 + t] * onrm;
    uint4 u;
    u.x = pack_half2(v[0], v[1]); u.y = pack_half2(v[2], v[3]);
    u.z = pack_half2(v[4], v[5]); u.w = pack_half2(v[6], v[7]);
    *reinterpret_cast<uint4*>(g_thf + (size_t)node * 256 + t * 32 + f0) = u;
}

// ---------------------------------------------------------------------------
// fp16 pull: accumulate 8 halves (one 16B chunk) into fp32 acc
template<bool SC>
__device__ __forceinline__ void acc8(const uint4 u, float s, float* a) {
    float2 f0 = __half22float2(*reinterpret_cast<const __half2*>(&u.x));
    float2 f1 = __half22float2(*reinterpret_cast<const __half2*>(&u.y));
    float2 f2 = __half22float2(*reinterpret_cast<const __half2*>(&u.z));
    float2 f3 = __half22float2(*reinterpret_cast<const __half2*>(&u.w));
    if (SC) {
        a[0] = fmaf(f0.x, s, a[0]); a[1] = fmaf(f0.y, s, a[1]);
        a[2] = fmaf(f1.x, s, a[2]); a[3] = fmaf(f1.y, s, a[3]);
        a[4] = fmaf(f2.x, s, a[4]); a[5] = fmaf(f2.y, s, a[5]);
        a[6] = fmaf(f3.x, s, a[6]); a[7] = fmaf(f3.y, s, a[7]);
    } else {
        a[0] += f0.x; a[1] += f0.y; a[2] += f1.x; a[3] += f1.y;
        a[4] += f2.x; a[5] += f2.y; a[6] += f3.x; a[7] += f3.y;
    }
}

// single-edge accumulate
template<int LC, int NCH, bool SRCSCALE>
__device__ __forceinline__ void pull_one(const __half* __restrict__ hin,
                                         int s0, int lane, float acc[][8]) {
    float c0 = SRCSCALE ? __ldg(&g_onorm[s0]) : 1.0f;
    const uint4* h0 = reinterpret_cast<const uint4*>(hin + (size_t)s0 * (LC * 8));
    #pragma unroll
    for (int j = 0; j < NCH; ++j) {
        int c = lane + j * 32;
        if (c < LC) {
            uint4 a = __ldg(&h0[c]);
            acc8<SRCSCALE>(a, c0, acc[j]);
        }
    }
}

// Pull (proven structure; esrc fetched as uint2 pairs at even indices)
template<int LC, int NCH, bool SRCSCALE>
__device__ __forceinline__ void pull_node_h(const __half* __restrict__ hin,
                                            int w, int lane, float acc[][8]) {
    int beg = __ldg(&g_offsets[w]);
    int end = __ldg(&g_offsets[w + 1]);
    #pragma unroll
    for (int j = 0; j < NCH; ++j)
        #pragma unroll
        for (int m = 0; m < 8; ++m) acc[j][m] = 0.0f;

    int e = beg;
    if ((e & 1) && e < end) {            // head peel to even alignment
        pull_one<LC, NCH, SRCSCALE>(hin, __ldg(&g_esrc[e]), lane, acc);
        ++e;
    }
    for (; e + 2 <= end; e += 2) {
        uint2 ss = __ldg(reinterpret_cast<const uint2*>(g_esrc) + (e >> 1));
        int s0 = (int)ss.x, s1 = (int)ss.y;
        float c0 = SRCSCALE ? __ldg(&g_onorm[s0]) : 1.0f;
        float c1 = SRCSCALE ? __ldg(&g_onorm[s1]) : 1.0f;
        const uint4* h0 = reinterpret_cast<const uint4*>(hin + (size_t)s0 * (LC * 8));
        const uint4* h1 = reinterpret_cast<const uint4*>(hin + (size_t)s1 * (LC * 8));
        #pragma unroll
        for (int j = 0; j < NCH; ++j) {
            int c = lane + j * 32;
            if (c < LC) {
                uint4 a = __ldg(&h0[c]);
                uint4 b = __ldg(&h1[c]);
                acc8<SRCSCALE>(a, c0, acc[j]);
                acc8<SRCSCALE>(b, c1, acc[j]);
            }
        }
    }
    if (e < end)                          // tail
        pull_one<LC, NCH, SRCSCALE>(hin, __ldg(&g_esrc[e]), lane, acc);
}

// Stage fp32 tile into padded smem with row offset TOFF
template<int LC, int NCH, int FIN, int RSF, int TOFF>
__device__ __forceinline__ void stage_tile(float* __restrict__ xrow, int lane,
                                           float acc[][8], float inrm) {
    constexpr int CPT = FIN / 8;   // chunks per t-row
    #pragma unroll
    for (int j = 0; j < NCH; ++j) {
        int c = lane + j * 32;
        if (c < LC) {
            int t = c / CPT, f0 = (c % CPT) * 8;
            float* p = xrow + (t + TOFF) * RSF + f0;
            float4 v0 = make_float4(acc[j][0] * inrm, acc[j][1] * inrm,
                                    acc[j][2] * inrm, acc[j][3] * inrm);
            float4 v1 = make_float4(acc[j][4] * inrm, acc[j][5] * inrm,
                                    acc[j][6] * inrm, acc[j][7] * inrm);
            *reinterpret_cast<float4*>(p)     = v0;
            *reinterpret_cast<float4*>(p + 4) = v1;
        }
    }
}

// ---------------------------------------------------------------------------
// Launch 3 (PROFILED): layer 1 = pull(thf) + matmul 32->40 relu -> fp16
// (unchanged from round 15 — pull-dominated)
__global__ __launch_bounds__(256)
void k_pullmm1(const float* __restrict__ b, uint2* __restrict__ yout) {
    constexpr int LC = 32, NCH = 1, FIN = 32, RSF = 36, OG = 10, P = 16;
    __shared__ __align__(16) float xsh[8][9 * RSF];

    int warp = threadIdx.x >> 5, lane = threadIdx.x & 31;
    int node = blockIdx.x * 8 + warp;

    float acc[NCH][8];
    pull_node_h<LC, NCH, false>(g_thf, node, lane, acc);
    if (lane < RSF) {                       // zero pad row 8
        xsh[warp][8 * RSF + lane] = 0.0f;
        if (lane + 32 < RSF) xsh[warp][8 * RSF + lane + 32] = 0.0f;
    }
    stage_tile<LC, NCH, FIN, RSF, 0>(xsh[warp], lane, acc, __ldg(&g_inorm[node]));
    __syncwarp();

    if (lane < 30) {
        int og = lane % OG, g = lane / OG;
        float onrm = __ldg(&g_onorm[node]);
        const ulonglong2* Wp = reinterpret_cast<const ulonglong2*>(g_W1p);
        float4 bv = reinterpret_cast<const float4*>(b)[og];
        unsigned long long a[4][3];
        #pragma unroll
        for (int k = 0; k < 3; ++k) {
            a[0][k] = f2pack(bv.x, 0.0f); a[1][k] = f2pack(bv.y, 0.0f);
            a[2][k] = f2pack(bv.z, 0.0f); a[3][k] = f2pack(bv.w, 0.0f);
        }
        const float* x0 = &xsh[warp][(g * 3 + 0) * RSF];
        const float* x1 = &xsh[warp][(g * 3 + 1) * RSF];
        const float* x2 = &xsh[warp][(g * 3 + 2) * RSF];   // zeros when g==2
        #pragma unroll
        for (int i4 = 0; i4 < FIN / 4; ++i4) {
            ulonglong2 xq0 = *reinterpret_cast<const ulonglong2*>(x0 + i4 * 4);
            ulonglong2 xq1 = *reinterpret_cast<const ulonglong2*>(x1 + i4 * 4);
            ulonglong2 xq2 = *reinterpret_cast<const ulonglong2*>(x2 + i4 * 4);
            #pragma unroll
            for (int pp = 0; pp < 2; ++pp) {
                int p = i4 * 2 + pp;
                ulonglong2 w0 = __ldg(&Wp[p * OG + og]);
                ulonglong2 w1 = __ldg(&Wp[P * OG + p * OG + og]);
                unsigned long long xv0 = pp ? xq0.y : xq0.x;
                unsigned long long xv1 = pp ? xq1.y : xq1.x;
                unsigned long long xv2 = pp ? xq2.y : xq2.x;
                ffma2(a[0][0], xv0, w0.x); ffma2(a[1][0], xv0, w0.y);
                ffma2(a[2][0], xv0, w1.x); ffma2(a[3][0], xv0, w1.y);
                ffma2(a[0][1], xv1, w0.x); ffma2(a[1][1], xv1, w0.y);
                ffma2(a[2][1], xv1, w1.x); ffma2(a[3][1], xv1, w1.y);
                ffma2(a[0][2], xv2, w0.x); ffma2(a[1][2], xv2, w0.y);
                ffma2(a[2][2], xv2, w1.x); ffma2(a[3][2], xv2, w1.y);
            }
        }
        #pragma unroll
        for (int k = 0; k < 3; ++k) {
            int t = g * 3 + k;
            if (t < T_DIM) {
                float o0 = fmaxf(f2sum(a[0][k]), 0.0f) * onrm;
                float o1 = fmaxf(f2sum(a[1][k]), 0.0f) * onrm;
                float o2 = fmaxf(f2sum(a[2][k]), 0.0f) * onrm;
                float o3 = fmaxf(f2sum(a[3][k]), 0.0f) * onrm;
                uint2 r; r.x = pack_half2(o0, o1); r.y = pack_half2(o2, o3);
                yout[(size_t)node * 80 + t * 10 + og] = r;
            }
        }
    }
}

// Launch 4: layer 2 = pull(fp16) + matmul 40->64 relu -> fp16.
// Epilogue: warps 0-3 each serve TWO staged nodes (lanes 0-15 node A,
// 16-31 node B, og=lane&15, all 8 t per lane) -> W wavefronts halved/node.
__global__ __launch_bounds__(256)
void k_pullmm2(const float* __restrict__ b, uint2* __restrict__ yout) {
    constexpr int LC = 40, NCH = 2, FIN = 40, RSF = 44, OG = 16, P = 20;
    __shared__ __align__(16) float xsh[8][T_DIM * RSF];

    int warp = threadIdx.x >> 5, lane = threadIdx.x & 31;
    int node = blockIdx.x * 8 + warp;

    float acc[NCH][8];
    pull_node_h<LC, NCH, false>(g_hbufB, node, lane, acc);
    stage_tile<LC, NCH, FIN, RSF, 0>(xsh[warp], lane, acc, __ldg(&g_inorm[node]));
    __syncthreads();

    if (warp < 4) {
        int side = lane >> 4, og = lane & 15;
        int local = warp * 2 + side;
        int node2 = blockIdx.x * 8 + local;
        float onrm = __ldg(&g_onorm[node2]);
        const ulonglong2* Wp = reinterpret_cast<const ulonglong2*>(g_W2p);
        float4 bv = reinterpret_cast<const float4*>(b)[og];
        unsigned long long a[4][8];
        #pragma unroll
        for (int t = 0; t < 8; ++t) {
            a[0][t] = f2pack(bv.x, 0.0f); a[1][t] = f2pack(bv.y, 0.0f);
            a[2][t] = f2pack(bv.z, 0.0f); a[3][t] = f2pack(bv.w, 0.0f);
        }
        const float* xb = xsh[local];
        #pragma unroll
        for (int i4 = 0; i4 < FIN / 4; ++i4) {
            ulonglong2 xq[8];
            #pragma unroll
            for (int t = 0; t < 8; ++t)
                xq[t] = *reinterpret_cast<const ulonglong2*>(xb + t * RSF + i4 * 4);
            #pragma unroll
            for (int pp = 0; pp < 2; ++pp) {
                int p = i4 * 2 + pp;
                ulonglong2 w0 = __ldg(&Wp[p * OG + og]);
                ulonglong2 w1 = __ldg(&Wp[P * OG + p * OG + og]);
                #pragma unroll
                for (int t = 0; t < 8; ++t) {
                    unsigned long long xv = pp ? xq[t].y : xq[t].x;
                    ffma2(a[0][t], xv, w0.x); ffma2(a[1][t], xv, w0.y);
                    ffma2(a[2][t], xv, w1.x); ffma2(a[3][t], xv, w1.y);
                }
            }
        }
        #pragma unroll
        for (int t = 0; t < 8; ++t) {
            float o0 = fmaxf(f2sum(a[0][t]), 0.0f) * onrm;
            float o1 = fmaxf(f2sum(a[1][t]), 0.0f) * onrm;
            float o2 = fmaxf(f2sum(a[2][t]), 0.0f) * onrm;
            float o3 = fmaxf(f2sum(a[3][t]), 0.0f) * onrm;
            uint2 r; r.x = pack_half2(o0, o1); r.y = pack_half2(o2, o3);
            yout[(size_t)node2 * 128 + t * 16 + og] = r;
        }
    }
}

// Launch 5: layer 3 = pull(fp16) + FUSED (matmul3 ∘ conv1d) via Wfp -> out fp32.
// Epilogue: warps 0-3 serve two nodes each (all 8 t per lane), rolling 8-row
// xq window covers padded rows 0..9. W wavefronts halved per node.
// Also self-restores the degree counters to zero for the next call.
__global__ __launch_bounds__(256)
void k_pullconv(float* __restrict__ out) {
    constexpr int LC = 64, NCH = 2, FIN = 64, RSF = 68, OG = 16, P = 96;
    __shared__ __align__(16) float xsh[8][10 * RSF];  // rows 0 and 9 zero pads
    __shared__ float osh[8][576];                     // [o][t] pad-9 staging

    int gid = blockIdx.x * blockDim.x + threadIdx.x;
    if (gid < N_NODES) { g_odeg[gid] = 0; g_indeg[gid] = 0; }

    int warp = threadIdx.x >> 5, lane = threadIdx.x & 31;
    int node = blockIdx.x * 8 + warp;

    float acc[NCH][8];
    pull_node_h<LC, NCH, false>(g_hbufA, node, lane, acc);
    #pragma unroll
    for (int j = lane; j < RSF; j += 32) {   // zero pad rows 0 (t=-1) and 9 (t=8)
        xsh[warp][j] = 0.0f;
        xsh[warp][9 * RSF + j] = 0.0f;
    }
    stage_tile<LC, NCH, FIN, RSF, 1>(xsh[warp], lane, acc, __ldg(&g_inorm[node]));
    __syncthreads();

    if (warp < 4) {
        int side = lane >> 4, og = lane & 15;
        int local = warp * 2 + side;
        const ulonglong2* Wp = reinterpret_cast<const ulonglong2*>(g_Wfp);
        unsigned long long a[4][8];
        #pragma unroll
        for (int t = 0; t < 8; ++t) {
            const float* bp = (t == 0) ? g_bias0 : (t == 7) ? g_bias7 : g_biasm;
            float4 bv = reinterpret_cast<const float4*>(bp)[og];
            a[0][t] = f2pack(bv.x, 0.0f); a[1][t] = f2pack(bv.y, 0.0f);
            a[2][t] = f2pack(bv.z, 0.0f); a[3][t] = f2pack(bv.w, 0.0f);
        }
        const float* xb = xsh[local];   // padded rows 0..9; out t reads rows t..t+2
        #pragma unroll
        for (int i4 = 0; i4 < 16; ++i4) {
            ulonglong2 xq[8];           // rolling window over rows, idx = row & 7
            #pragma unroll
            for (int r = 0; r < 8; ++r)
                xq[r] = *reinterpret_cast<const ulonglong2*>(xb + r * RSF + i4 * 4);
            #pragma unroll
            for (int kc = 0; kc < 3; ++kc) {
                if (kc > 0) {           // bring in row 7+kc (8 then 9)
                    int r = 7 + kc;
                    xq[r & 7] = *reinterpret_cast<const ulonglong2*>(
                        xb + r * RSF + i4 * 4);
                }
                #pragma unroll
                for (int pp = 0; pp < 2; ++pp) {
                    int p = kc * 32 + i4 * 2 + pp;
                    ulonglong2 w0 = __ldg(&Wp[p * OG + og]);
                    ulonglong2 w1 = __ldg(&Wp[P * OG + p * OG + og]);
                    #pragma unroll
                    for (int t = 0; t < 8; ++t) {
                        const ulonglong2& q = xq[(t + kc) & 7];
                        unsigned long long xv = pp ? q.y : q.x;
                        ffma2(a[0][t], xv, w0.x); ffma2(a[1][t], xv, w0.y);
                        ffma2(a[2][t], xv, w1.x); ffma2(a[3][t], xv, w1.y);
                    }
                }
            }
        }
        int o0 = og * 4;
        #pragma unroll
        for (int t = 0; t < 8; ++t) {
            osh[local][(o0 + 0) * 9 + t] = f2sum(a[0][t]);
            osh[local][(o0 + 1) * 9 + t] = f2sum(a[1][t]);
            osh[local][(o0 + 2) * 9 + t] = f2sum(a[2][t]);
            osh[local][(o0 + 3) * 9 + t] = f2sum(a[3][t]);
        }
    }
    __syncthreads();

    float* ob = out + (size_t)node * 512;
    #pragma unroll
    for (int k = 0; k < 16; ++k) {
        int j = lane + k * 32;
        ob[j] = osh[warp][(j >> 3) * 9 + (j & 7)];
    }
}

// ---------------------------------------------------------------------------
extern "C" void kernel_launch(void* const* d_in, const int* in_sizes, int n_in,
                              void* d_out, int out_size) {
    const float* tf  = (const float*)d_in[0];
    const int*   src = (const int*)  d_in[1];
    const int*   dst = (const int*)  d_in[2];
    const float* W1  = (const float*)d_in[3];
    const float* b1  = (const float*)d_in[4];
    const float* W2  = (const float*)d_in[5];
    const float* b2  = (const float*)d_in[6];
    const float* W3  = (const float*)d_in[7];
    const float* b3  = (const float*)d_in[8];
    const float* Wc  = (const float*)d_in[9];
    const float* bc  = (const float*)d_in[10];
    float* out = (float*)d_out;

    uint2 *hbufB, *hbufA;
    cudaGetSymbolAddress((void**)&hbufB, g_hbufB);
    cudaGetSymbolAddress((void**)&hbufA, g_hbufA);

    const int TB = 256;

    // 0: histogram + all weight preprocessing
    k_degprep<<<cdiv(N_EDGES + 16192, TB), TB>>>(src, dst, W1, W2, W3, Wc, b3, bc);
    // 1: scan + norms
    k_scanall<<<1, 1024>>>();
    // 2: CSR fill + tf transpose*onorm -> fp16
    k_fill<<<N_NODES / 8, TB>>>(src, dst, tf);

    k_pullmm1<<<N_NODES / 8, TB>>>(b1, hbufB);           // 3 (PROFILED)
    k_pullmm2<<<N_NODES / 8, TB>>>(b2, hbufA);           // 4
    k_pullconv<<<N_NODES / 8, TB>>>(out);                // 5
}

// round 17
// speedup vs baseline: 1.9018x; 1.9018x over previous
#include <cuda_runtime.h>
#include <cuda_fp16.h>
#include <cstdint>

#define N_NODES 50000
#define N_EDGES 800000
#define T_DIM   8
#define NF_IN   32
#define NH1     40
#define NH2     64
#define NF_OUT  64

// Scratch (device globals; allocation-free per harness rules)
__device__ __align__(16) __half g_thf  [N_NODES * 256];   // tf^T * onorm, [n][t][32], fp16
__device__ __align__(16) __half g_hbufB[N_NODES * 320];   // layer1 out [n][t][40], fp16
__device__ __align__(16) __half g_hbufA[N_NODES * 512];   // layer2 out [n][t][64], fp16
__device__ float g_onorm[N_NODES];
__device__ float g_inorm[N_NODES];
__device__ int   g_odeg [N_NODES];   // zero on entry (static init + self-restore)
__device__ int   g_indeg[N_NODES];   // zero on entry (static init + self-restore)
__device__ int   g_offsets[N_NODES + 1];
__device__ int   g_cursor [N_NODES];
__device__ __align__(16) int g_esrc [N_EDGES];
// i-pair-interleaved weights for mm1/mm2 FFMA2 epilogues
__device__ __align__(16) float g_W1p[2 * 16 * 10 * 4];    // 1280
__device__ __align__(16) float g_W2p[2 * 20 * 16 * 4];    // 2560
// fused conv weight fp16 row-major [k=192][o=64] for HMMA
__device__ __align__(16) __half g_Wfh[192 * 64];
__device__ __align__(16) float g_biasm[64];               // bias for t in 1..6
__device__ __align__(16) float g_bias0[64];               // bias for t == 0
__device__ __align__(16) float g_bias7[64];               // bias for t == 7

static inline int cdiv(int a, int b) { return (a + b - 1) / b; }

__device__ __forceinline__ unsigned int pack_half2(float a, float b) {
    __half2 h = __floats2half2_rn(a, b);
    return *reinterpret_cast<unsigned int*>(&h);
}

// ---- packed f32x2 helpers (Blackwell FFMA2) ----
__device__ __forceinline__ unsigned long long f2pack(float lo, float hi) {
    unsigned long long r;
    asm("mov.b64 %0, {%1, %2};" : "=l"(r) : "f"(lo), "f"(hi));
    return r;
}
__device__ __forceinline__ void f2unpack(unsigned long long v, float& lo, float& hi) {
    asm("mov.b64 {%0, %1}, %2;" : "=f"(lo), "=f"(hi) : "l"(v));
}
__device__ __forceinline__ void ffma2(unsigned long long& d,
                                      unsigned long long a, unsigned long long b) {
    asm("fma.rn.f32x2 %0, %1, %2, %3;" : "=l"(d) : "l"(a), "l"(b), "l"(d));
}
__device__ __forceinline__ float f2sum(unsigned long long v) {
    float lo, hi; f2unpack(v, lo, hi); return lo + hi;
}

// ---- HMMA helpers ----
__device__ __forceinline__ unsigned sm2u(const void* p) {
    return (unsigned)__cvta_generic_to_shared(p);
}
__device__ __forceinline__ void ldmA_x4(unsigned& r0, unsigned& r1,
                                        unsigned& r2, unsigned& r3, unsigned addr) {
    asm volatile("ldmatrix.sync.aligned.m8n8.x4.shared.b16 {%0,%1,%2,%3}, [%4];"
                 : "=r"(r0), "=r"(r1), "=r"(r2), "=r"(r3) : "r"(addr));
}
__device__ __forceinline__ void ldmB_x2t(unsigned& r0, unsigned& r1, unsigned addr) {
    asm volatile("ldmatrix.sync.aligned.m8n8.x2.trans.shared.b16 {%0,%1}, [%2];"
                 : "=r"(r0), "=r"(r1) : "r"(addr));
}
__device__ __forceinline__ void mma16816(float& c0, float& c1, float& c2, float& c3,
                                         unsigned a0, unsigned a1, unsigned a2, unsigned a3,
                                         unsigned b0, unsigned b1) {
    asm volatile("mma.sync.aligned.m16n8k16.row.col.f32.f16.f16.f32 "
                 "{%0,%1,%2,%3}, {%4,%5,%6,%7}, {%8,%9}, {%0,%1,%2,%3};"
                 : "+f"(c0), "+f"(c1), "+f"(c2), "+f"(c3)
                 : "r"(a0), "r"(a1), "r"(a2), "r"(a3), "r"(b0), "r"(b1));
}

// ---------------------------------------------------------------------------
// Launch 0: degree histogram (gid < N_EDGES) + weight preprocessing (rest).
__global__ void k_degprep(const int* __restrict__ src, const int* __restrict__ dst,
                          const float* __restrict__ W1, const float* __restrict__ W2,
                          const float* __restrict__ W3, const float* __restrict__ Wc,
                          const float* __restrict__ b3, const float* __restrict__ bc) {
    int gid = blockIdx.x * blockDim.x + threadIdx.x;
    if (gid < N_EDGES) {
        atomicAdd(&g_odeg[src[gid]], 1);
        atomicAdd(&g_indeg[dst[gid]], 1);
        return;
    }
    int j = gid - N_EDGES;
    if (j < 12288) {
        // Wfh fp16 row-major [k=kc*64+i][o]: Wf = sum_q W3[i][q] * Wc[o][q][kc]
        int kidx = j >> 6, o = j & 63;
        int kc = kidx >> 6, ii = kidx & 63;
        const float* w3r = W3 + ii * 64;
        const float* wcr = Wc + o * 192 + kc;   // Wc[o][q][kc], stride 3 over q
        float s = 0.0f;
        #pragma unroll 8
        for (int q = 0; q < 64; ++q)
            s = fmaf(w3r[q], wcr[q * 3], s);
        g_Wfh[j] = __float2half(s);
    } else if (j < 12288 + 64) {
        int o = j - 12288;
        const float* wcr = Wc + o * 192;
        float B0 = 0.0f, B1 = 0.0f, B2 = 0.0f;
        #pragma unroll 8
        for (int q = 0; q < 64; ++q) {
            float bq = b3[q];
            B0 = fmaf(bq, wcr[q * 3 + 0], B0);
            B1 = fmaf(bq, wcr[q * 3 + 1], B1);
            B2 = fmaf(bq, wcr[q * 3 + 2], B2);
        }
        float base = bc[o];
        g_biasm[o] = base + B0 + B1 + B2;
        g_bias0[o] = base + B1 + B2;       // t=0: k=0 invalid
        g_bias7[o] = base + B0 + B1;       // t=7: k=2 invalid
    } else if (j < 12288 + 64 + 1280) {
        int f = j - 12352;                 // W1p: P=16, OG=10
        int half = f / 640, r = f % 640;
        int p = r / 40, rr = r % 40;
        int og = rr / 4, c = rr & 3;
        int i = 2 * p + (c & 1);
        int o = og * 4 + half * 2 + (c >> 1);
        g_W1p[f] = W1[i * NH1 + o];
    } else if (j < 12288 + 64 + 1280 + 2560) {
        int f = j - 13632;                 // W2p: P=20, OG=16
        int half = f / 1280, r = f % 1280;
        int p = r / 64, rr = r % 64;
        int og = rr / 4, c = rr & 3;
        int i = 2 * p + (c & 1);
        int o = og * 4 + half * 2 + (c >> 1);
        g_W2p[f] = W2[i * NH2 + o];
    }
}

// Launch 1: single-block CSR prologue (scan + norms — proven)
__global__ void k_scanall() {
    __shared__ int wsum[32];
    __shared__ int s_carry;
    int lane = threadIdx.x & 31, wid = threadIdx.x >> 5;

    if (threadIdx.x == 0) s_carry = 0;
    __syncthreads();

    for (int base = 0; base < N_NODES; base += 1024) {
        int idx = base + threadIdx.x;
        int v = (idx < N_NODES) ? g_indeg[idx] : 0;
        int x = v;
        #pragma unroll
        for (int o = 1; o < 32; o <<= 1) {
            int y = __shfl_up_sync(0xffffffffu, x, o);
            if (lane >= o) x += y;
        }
        if (lane == 31) wsum[wid] = x;
        __syncthreads();
        if (wid == 0) {
            int s = wsum[lane];
            #pragma unroll
            for (int o = 1; o < 32; o <<= 1) {
                int y = __shfl_up_sync(0xffffffffu, s, o);
                if (lane >= o) s += y;
            }
            wsum[lane] = s;
        }
        __syncthreads();
        int carry = s_carry;
        int wbase = (wid > 0) ? wsum[wid - 1] : 0;
        int excl = carry + wbase + x - v;
        if (idx < N_NODES) {
            g_offsets[idx] = excl;
            g_cursor[idx]  = excl;
            g_onorm[idx] = rsqrtf(fmaxf((float)g_odeg[idx], 1.0f));
            g_inorm[idx] = rsqrtf(fmaxf((float)v, 1.0f));
        }
        __syncthreads();
        if (threadIdx.x == 1023) s_carry = carry + wbase + x;
        __syncthreads();
    }
    if (threadIdx.x == 0) g_offsets[N_NODES] = s_carry;
}

// Launch 2: fill CSR (gid < N_EDGES) + tf transpose * onorm -> fp16 (all blocks)
__global__ void k_fill(const int* __restrict__ src, const int* __restrict__ dst,
                       const float* __restrict__ tf) {
    __shared__ float sh[8][32 * 9];     // per-warp node tile, padded [f][t]
    int gid = blockIdx.x * blockDim.x + threadIdx.x;
    if (gid < N_EDGES) {                // first 3125 blocks
        int pos = atomicAdd(&g_cursor[dst[gid]], 1);
        g_esrc[pos] = src[gid];
    }

    int w = threadIdx.x >> 5, lane = threadIdx.x & 31;
    int node = blockIdx.x * 8 + w;      // 6250*8 = 50000 exactly
    const float4* src4 = reinterpret_cast<const float4*>(tf + (size_t)node * 256);
    #pragma unroll
    for (int h = 0; h < 2; ++h) {
        float4 v = __ldg(&src4[h * 32 + lane]);
        int l = (h * 32 + lane) * 4;    // linear [f][t] index
        int f = l >> 3, t = l & 7;
        float* p = &sh[w][f * 9 + t];
        p[0] = v.x; p[1] = v.y; p[2] = v.z; p[3] = v.w;
    }
    __syncwarp();
    float onrm = __ldg(&g_onorm[node]);
    int t = lane >> 2, f0 = (lane & 3) * 8;
    float v[8];
    #pragma unroll
    for (int m = 0; m < 8; ++m) v[m] = sh[w][(f0 + m) * 9 + t] * onrm;
    uint4 u;
    u.x = pack_half2(v[0], v[1]); u.y = pack_half2(v[2], v[3]);
    u.z = pack_half2(v[4], v[5]); u.w = pack_half2(v[6], v[7]);
    *reinterpret_cast<uint4*>(g_thf + (size_t)node * 256 + t * 32 + f0) = u;
}

// ---------------------------------------------------------------------------
// fp16 pull: accumulate 8 halves (one 16B chunk) into fp32 acc
template<bool SC>
__device__ __forceinline__ void acc8(const uint4 u, float s, float* a) {
    float2 f0 = __half22float2(*reinterpret_cast<const __half2*>(&u.x));
    float2 f1 = __half22float2(*reinterpret_cast<const __half2*>(&u.y));
    float2 f2 = __half22float2(*reinterpret_cast<const __half2*>(&u.z));
    float2 f3 = __half22float2(*reinterpret_cast<const __half2*>(&u.w));
    if (SC) {
        a[0] = fmaf(f0.x, s, a[0]); a[1] = fmaf(f0.y, s, a[1]);
        a[2] = fmaf(f1.x, s, a[2]); a[3] = fmaf(f1.y, s, a[3]);
        a[4] = fmaf(f2.x, s, a[4]); a[5] = fmaf(f2.y, s, a[5]);
        a[6] = fmaf(f3.x, s, a[6]); a[7] = fmaf(f3.y, s, a[7]);
    } else {
        a[0] += f0.x; a[1] += f0.y; a[2] += f1.x; a[3] += f1.y;
        a[4] += f2.x; a[5] += f2.y; a[6] += f3.x; a[7] += f3.y;
    }
}

// single-edge accumulate
template<int LC, int NCH, bool SRCSCALE>
__device__ __forceinline__ void pull_one(const __half* __restrict__ hin,
                                         int s0, int lane, float acc[][8]) {
    float c0 = SRCSCALE ? __ldg(&g_onorm[s0]) : 1.0f;
    const uint4* h0 = reinterpret_cast<const uint4*>(hin + (size_t)s0 * (LC * 8));
    #pragma unroll
    for (int j = 0; j < NCH; ++j) {
        int c = lane + j * 32;
        if (c < LC) {
            uint4 a = __ldg(&h0[c]);
            acc8<SRCSCALE>(a, c0, acc[j]);
        }
    }
}

// Pull (proven structure; esrc fetched as uint2 pairs at even indices)
template<int LC, int NCH, bool SRCSCALE>
__device__ __forceinline__ void pull_node_h(const __half* __restrict__ hin,
                                            int w, int lane, float acc[][8]) {
    int beg = __ldg(&g_offsets[w]);
    int end = __ldg(&g_offsets[w + 1]);
    #pragma unroll
    for (int j = 0; j < NCH; ++j)
        #pragma unroll
        for (int m = 0; m < 8; ++m) acc[j][m] = 0.0f;

    int e = beg;
    if ((e & 1) && e < end) {            // head peel to even alignment
        pull_one<LC, NCH, SRCSCALE>(hin, __ldg(&g_esrc[e]), lane, acc);
        ++e;
    }
    for (; e + 2 <= end; e += 2) {
        uint2 ss = __ldg(reinterpret_cast<const uint2*>(g_esrc) + (e >> 1));
        int s0 = (int)ss.x, s1 = (int)ss.y;
        float c0 = SRCSCALE ? __ldg(&g_onorm[s0]) : 1.0f;
        float c1 = SRCSCALE ? __ldg(&g_onorm[s1]) : 1.0f;
        const uint4* h0 = reinterpret_cast<const uint4*>(hin + (size_t)s0 * (LC * 8));
        const uint4* h1 = reinterpret_cast<const uint4*>(hin + (size_t)s1 * (LC * 8));
        #pragma unroll
        for (int j = 0; j < NCH; ++j) {
            int c = lane + j * 32;
            if (c < LC) {
                uint4 a = __ldg(&h0[c]);
                uint4 b = __ldg(&h1[c]);
                acc8<SRCSCALE>(a, c0, acc[j]);
                acc8<SRCSCALE>(b, c1, acc[j]);
            }
        }
    }
    if (e < end)                          // tail
        pull_one<LC, NCH, SRCSCALE>(hin, __ldg(&g_esrc[e]), lane, acc);
}

// Stage fp32 tile into padded smem with row offset TOFF
template<int LC, int NCH, int FIN, int RSF, int TOFF>
__device__ __forceinline__ void stage_tile(float* __restrict__ xrow, int lane,
                                           float acc[][8], float inrm) {
    constexpr int CPT = FIN / 8;   // chunks per t-row
    #pragma unroll
    for (int j = 0; j < NCH; ++j) {
        int c = lane + j * 32;
        if (c < LC) {
            int t = c / CPT, f0 = (c % CPT) * 8;
            float* p = xrow + (t + TOFF) * RSF + f0;
            float4 v0 = make_float4(acc[j][0] * inrm, acc[j][1] * inrm,
                                    acc[j][2] * inrm, acc[j][3] * inrm);
            float4 v1 = make_float4(acc[j][4] * inrm, acc[j][5] * inrm,
                                    acc[j][6] * inrm, acc[j][7] * inrm);
            *reinterpret_cast<float4*>(p)     = v0;
            *reinterpret_cast<float4*>(p + 4) = v1;
        }
    }
}

// ---------------------------------------------------------------------------
// Launch 3 (PROFILED): layer 1 = pull(thf) + matmul 32->40 relu -> fp16
// (round-15 exact — pull-dominated)
__global__ __launch_bounds__(256)
void k_pullmm1(const float* __restrict__ b, uint2* __restrict__ yout) {
    constexpr int LC = 32, NCH = 1, FIN = 32, RSF = 36, OG = 10, P = 16;
    __shared__ __align__(16) float xsh[8][9 * RSF];

    int warp = threadIdx.x >> 5, lane = threadIdx.x & 31;
    int node = blockIdx.x * 8 + warp;

    float acc[NCH][8];
    pull_node_h<LC, NCH, false>(g_thf, node, lane, acc);
    if (lane < RSF) {                       // zero pad row 8
        xsh[warp][8 * RSF + lane] = 0.0f;
        if (lane + 32 < RSF) xsh[warp][8 * RSF + lane + 32] = 0.0f;
    }
    stage_tile<LC, NCH, FIN, RSF, 0>(xsh[warp], lane, acc, __ldg(&g_inorm[node]));
    __syncwarp();

    if (lane < 30) {
        int og = lane % OG, g = lane / OG;
        float onrm = __ldg(&g_onorm[node]);
        const ulonglong2* Wp = reinterpret_cast<const ulonglong2*>(g_W1p);
        float4 bv = reinterpret_cast<const float4*>(b)[og];
        unsigned long long a[4][3];
        #pragma unroll
        for (int k = 0; k < 3; ++k) {
            a[0][k] = f2pack(bv.x, 0.0f); a[1][k] = f2pack(bv.y, 0.0f);
            a[2][k] = f2pack(bv.z, 0.0f); a[3][k] = f2pack(bv.w, 0.0f);
        }
        const float* x0 = &xsh[warp][(g * 3 + 0) * RSF];
        const float* x1 = &xsh[warp][(g * 3 + 1) * RSF];
        const float* x2 = &xsh[warp][(g * 3 + 2) * RSF];   // zeros when g==2
        #pragma unroll
        for (int i4 = 0; i4 < FIN / 4; ++i4) {
            ulonglong2 xq0 = *reinterpret_cast<const ulonglong2*>(x0 + i4 * 4);
            ulonglong2 xq1 = *reinterpret_cast<const ulonglong2*>(x1 + i4 * 4);
            ulonglong2 xq2 = *reinterpret_cast<const ulonglong2*>(x2 + i4 * 4);
            #pragma unroll
            for (int pp = 0; pp < 2; ++pp) {
                int p = i4 * 2 + pp;
                ulonglong2 w0 = __ldg(&Wp[p * OG + og]);
                ulonglong2 w1 = __ldg(&Wp[P * OG + p * OG + og]);
                unsigned long long xv0 = pp ? xq0.y : xq0.x;
                unsigned long long xv1 = pp ? xq1.y : xq1.x;
                unsigned long long xv2 = pp ? xq2.y : xq2.x;
                ffma2(a[0][0], xv0, w0.x); ffma2(a[1][0], xv0, w0.y);
                ffma2(a[2][0], xv0, w1.x); ffma2(a[3][0], xv0, w1.y);
                ffma2(a[0][1], xv1, w0.x); ffma2(a[1][1], xv1, w0.y);
                ffma2(a[2][1], xv1, w1.x); ffma2(a[3][1], xv1, w1.y);
                ffma2(a[0][2], xv2, w0.x); ffma2(a[1][2], xv2, w0.y);
                ffma2(a[2][2], xv2, w1.x); ffma2(a[3][2], xv2, w1.y);
            }
        }
        #pragma unroll
        for (int k = 0; k < 3; ++k) {
            int t = g * 3 + k;
            if (t < T_DIM) {
                float o0 = fmaxf(f2sum(a[0][k]), 0.0f) * onrm;
                float o1 = fmaxf(f2sum(a[1][k]), 0.0f) * onrm;
                float o2 = fmaxf(f2sum(a[2][k]), 0.0f) * onrm;
                float o3 = fmaxf(f2sum(a[3][k]), 0.0f) * onrm;
                uint2 r; r.x = pack_half2(o0, o1); r.y = pack_half2(o2, o3);
                yout[(size_t)node * 80 + t * 10 + og] = r;
            }
        }
    }
}

// Launch 4: layer 2 = pull(fp16) + matmul 40->64 relu -> fp16 (round-15 exact)
__global__ __launch_bounds__(256)
void k_pullmm2(const float* __restrict__ b, uint2* __restrict__ yout) {
    constexpr int LC = 40, NCH = 2, FIN = 40, RSF = 44, OG = 16, P = 20;
    __shared__ __align__(16) float xsh[8][T_DIM * RSF];

    int warp = threadIdx.x >> 5, lane = threadIdx.x & 31;
    int node = blockIdx.x * 8 + warp;

    float acc[NCH][8];
    pull_node_h<LC, NCH, false>(g_hbufB, node, lane, acc);
    stage_tile<LC, NCH, FIN, RSF, 0>(xsh[warp], lane, acc, __ldg(&g_inorm[node]));
    __syncwarp();

    int og = lane & 15, g = lane >> 4;
    float onrm = __ldg(&g_onorm[node]);
    const ulonglong2* Wp = reinterpret_cast<const ulonglong2*>(g_W2p);
    float4 bv = reinterpret_cast<const float4*>(b)[og];
    unsigned long long a[4][4];
    #pragma unroll
    for (int k = 0; k < 4; ++k) {
        a[0][k] = f2pack(bv.x, 0.0f); a[1][k] = f2pack(bv.y, 0.0f);
        a[2][k] = f2pack(bv.z, 0.0f); a[3][k] = f2pack(bv.w, 0.0f);
    }
    const float* xb = &xsh[warp][(g * 4) * RSF];
    #pragma unroll
    for (int i4 = 0; i4 < FIN / 4; ++i4) {
        ulonglong2 xq[4];
        #pragma unroll
        for (int k = 0; k < 4; ++k)
            xq[k] = *reinterpret_cast<const ulonglong2*>(xb + k * RSF + i4 * 4);
        #pragma unroll
        for (int pp = 0; pp < 2; ++pp) {
            int p = i4 * 2 + pp;
            ulonglong2 w0 = __ldg(&Wp[p * OG + og]);
            ulonglong2 w1 = __ldg(&Wp[P * OG + p * OG + og]);
            #pragma unroll
            for (int k = 0; k < 4; ++k) {
                unsigned long long xv = pp ? xq[k].y : xq[k].x;
                ffma2(a[0][k], xv, w0.x); ffma2(a[1][k], xv, w0.y);
                ffma2(a[2][k], xv, w1.x); ffma2(a[3][k], xv, w1.y);
            }
        }
    }
    #pragma unroll
    for (int k = 0; k < 4; ++k) {
        int t = g * 4 + k;
        float o0 = fmaxf(f2sum(a[0][k]), 0.0f) * onrm;
        float o1 = fmaxf(f2sum(a[1][k]), 0.0f) * onrm;
        float o2 = fmaxf(f2sum(a[2][k]), 0.0f) * onrm;
        float o3 = fmaxf(f2sum(a[3][k]), 0.0f) * onrm;
        uint2 r; r.x = pack_half2(o0, o1); r.y = pack_half2(o2, o3);
        yout[(size_t)node * 128 + t * 16 + og] = r;
    }
}

// Launch 5: layer 3 = pull(fp16) + HMMA conv via Wfh -> out fp32.
// Per node: padded fp16 tile rows 0..9 (t=-1..8). Conv as GEMM:
//   C[16 rows(2 nodes x 8t), 64] = A[16,192] @ Wfh[192,64]
// A fragments: ldmatrix from tile at row (t + kc). Each warp owns one 8-wide
// o-tile, caches 12 B fragments in regs, loops 4 node pairs.
// Dynamic smem: xshh (fp16 tiles) | wsh (Wfh copy) | osh (fp32 staging).
#define RSH   72                    // fp16 tile row stride (halfs)
#define XSH_B (8 * 10 * RSH * 2)    // 11520
#define WSH_B (192 * 64 * 2)        // 24576
#define OSH_B (8 * 576 * 4)         // 18432
#define CONV_SMEM (XSH_B + WSH_B + OSH_B)

__global__ __launch_bounds__(256)
void k_pullconv(float* __restrict__ out) {
    constexpr int LC = 64, NCH = 2;
    extern __shared__ __align__(16) unsigned char dsm[];
    __half (*xshh)[10 * RSH] = reinterpret_cast<__half(*)[10 * RSH]>(dsm);
    __half* wsh = reinterpret_cast<__half*>(dsm + XSH_B);
    float (*osh)[576] = reinterpret_cast<float(*)[576]>(dsm + XSH_B + WSH_B);

    int tid = threadIdx.x;
    int gid = blockIdx.x * blockDim.x + tid;
    if (gid < N_NODES) { g_odeg[gid] = 0; g_indeg[gid] = 0; }   // self-restore

    // Wfh gmem -> smem (1536 uint4 over 256 threads)
    {
        const uint4* wg = reinterpret_cast<const uint4*>(g_Wfh);
        uint4* ws = reinterpret_cast<uint4*>(wsh);
        #pragma unroll
        for (int i = 0; i < 6; ++i)
            ws[tid + i * 256] = __ldg(&wg[tid + i * 256]);
    }

    int warp = tid >> 5, lane = tid & 31;
    int node = blockIdx.x * 8 + warp;

    float acc[NCH][8];
    pull_node_h<LC, NCH, false>(g_hbufA, node, lane, acc);

    // zero pad rows 0 (t=-1) and 9 (t=8)
    for (int j = lane; j < RSH; j += 32) {
        xshh[warp][j] = __float2half(0.0f);
        xshh[warp][9 * RSH + j] = __float2half(0.0f);
    }
    // stage fp16: chunk c -> t = c/8, f0 = (c%8)*8, padded row t+1
    {
        float inrm = __ldg(&g_inorm[node]);
        #pragma unroll
        for (int j = 0; j < NCH; ++j) {
            int c = lane + j * 32;
            int t = c >> 3, f0 = (c & 7) * 8;
            uint4 u;
            u.x = pack_half2(acc[j][0] * inrm, acc[j][1] * inrm);
            u.y = pack_half2(acc[j][2] * inrm, acc[j][3] * inrm);
            u.z = pack_half2(acc[j][4] * inrm, acc[j][5] * inrm);
            u.w = pack_half2(acc[j][6] * inrm, acc[j][7] * inrm);
            *reinterpret_cast<uint4*>(&xshh[warp][(t + 1) * RSH + f0]) = u;
        }
    }
    __syncthreads();

    // B fragments: warp owns o-tile [warp*8, warp*8+8); 12 k-steps cached in regs
    unsigned B0[12], B1[12];
    {
        unsigned wbase = sm2u(wsh);
        #pragma unroll
        for (int s = 0; s < 12; ++s) {
            unsigned addr = wbase + ((s * 16 + (lane & 15)) * 64 + warp * 8) * 2;
            ldmB_x2t(B0[s], B1[s], addr);
        }
    }

    // node-pair loop: A rows 0-7 = node (2p) t, rows 8-15 = node (2p+1) t
    int nodesel = (lane >> 3) & 1;          // 0: rows 0-7, 1: rows 8-15
    int arow    = lane & 7;                 // t
    int ahalf   = ((lane >> 4) & 1) * 8;    // k 0-7 vs 8-15 (halfs)
    #pragma unroll
    for (int pair = 0; pair < 4; ++pair) {
        float c0 = 0.f, c1 = 0.f, c2 = 0.f, c3 = 0.f;
        const __half* xb = xshh[pair * 2 + nodesel];
        #pragma unroll
        for (int s = 0; s < 12; ++s) {
            int kc = s >> 2, i16 = s & 3;
            unsigned addr = sm2u(&xb[(arow + kc) * RSH + ahalf + i16 * 16]);
            unsigned a0, a1, a2, a3;
            ldmA_x4(a0, a1, a2, a3, addr);
            mma16816(c0, c1, c2, c3, a0, a1, a2, a3, B0[s], B1[s]);
        }
        int o = warp * 8 + (lane & 3) * 2;
        int t = lane >> 2;
        osh[pair * 2    ][o * 9 + t]       = c0;
        osh[pair * 2    ][(o + 1) * 9 + t] = c1;
        osh[pair * 2 + 1][o * 9 + t]       = c2;
        osh[pair * 2 + 1][(o + 1) * 9 + t] = c3;
    }
    __syncthreads();

    // copy own node's tile + bias(t,o) -> out [n][o][t]
    float* ob = out + (size_t)node * 512;
    #pragma unroll
    for (int k = 0; k < 16; ++k) {
        int j = lane + k * 32;
        int o = j >> 3, t = j & 7;
        const float* bp = (t == 0) ? g_bias0 : (t == 7) ? g_bias7 : g_biasm;
        ob[j] = osh[warp][o * 9 + t] + __ldg(&bp[o]);
    }
}

// ---------------------------------------------------------------------------
extern "C" void kernel_launch(void* const* d_in, const int* in_sizes, int n_in,
                              void* d_out, int out_size) {
    const float* tf  = (const float*)d_in[0];
    const int*   src = (const int*)  d_in[1];
    const int*   dst = (const int*)  d_in[2];
    const float* W1  = (const float*)d_in[3];
    const float* b1  = (const float*)d_in[4];
    const float* W2  = (const float*)d_in[5];
    const float* b2  = (const float*)d_in[6];
    const float* W3  = (const float*)d_in[7];
    const float* b3  = (const float*)d_in[8];
    const float* Wc  = (const float*)d_in[9];
    const float* bc  = (const float*)d_in[10];
    float* out = (float*)d_out;

    uint2 *hbufB, *hbufA;
    cudaGetSymbolAddress((void**)&hbufB, g_hbufB);
    cudaGetSymbolAddress((void**)&hbufA, g_hbufA);

    // dynamic smem opt-in (host API, idempotent, capture-safe)
    cudaFuncSetAttribute(k_pullconv, cudaFuncAttributeMaxDynamicSharedMemorySize,
                         CONV_SMEM);

    const int TB = 256;

    // 0: histogram + all weight preprocessing
    k_degprep<<<cdiv(N_EDGES + 16192, TB), TB>>>(src, dst, W1, W2, W3, Wc, b3, bc);
    // 1: scan + norms
    k_scanall<<<1, 1024>>>();
    // 2: CSR fill + tf transpose*onorm -> fp16
    k_fill<<<N_NODES / 8, TB>>>(src, dst, tf);

    k_pullmm1<<<N_NODES / 8, TB>>>(b1, hbufB);               // 3 (PROFILED)
    k_pullmm2<<<N_NODES / 8, TB>>>(b2, hbufA);               // 4
    k_pullconv<<<N_NODES / 8, TB, CONV_SMEM>>>(out);         // 5 (HMMA conv)
}